// round 9
// baseline (speedup 1.0000x reference)
#include <cuda_runtime.h>
#include <cstdint>

#define N_IMG 2
#define CIN   2048
#define FOUT  512
#define H     64
#define W     64
#define HW    4096
#define NCELL 50
#define EPSV  1e-5f
#define SLOPE 0.01f

// ---------------- device scratch ----------------
__device__ float g_poolT[N_IMG][NCELL][CIN];
__device__ float g_prior[4][N_IMG][FOUT][36];
__device__ float g_inp[(size_t)N_IMG * 66 * 66 * 2048];   // NHWC padded feats (tf32)
__device__ float g_wt[(size_t)9 * FOUT * 2048];           // feats weights [tap][o][c] (tf32)
__device__ float g_qa[N_IMG][FOUT][480];                  // prior-collapsed A (tf32)
__device__ float g_lam[N_IMG][HW][480];                   // geometric weights (tf32)
__device__ float g_conv[N_IMG][FOUT][HW];
__device__ float g_ostat[FOUT][2];

__device__ __forceinline__ uint32_t smem_u32(const void* p) {
    uint32_t a;
    asm("{ .reg .u64 t; cvta.to.shared.u64 t, %1; cvt.u32.u64 %0, t; }" : "=r"(a) : "l"(p));
    return a;
}
__device__ __forceinline__ float to_tf32(float x) {
    uint32_t u;
    asm("cvt.rna.tf32.f32 %0, %1;" : "=r"(u) : "f"(x));
    return __uint_as_float(u);
}
__device__ __forceinline__ void cp16(uint32_t saddr, const float* gaddr) {
    asm volatile("cp.async.cg.shared.global [%0], [%1], 16;" :: "r"(saddr), "l"(gaddr));
}
#define CP_COMMIT() asm volatile("cp.async.commit_group;" ::: "memory")
#define CP_WAIT1()  asm volatile("cp.async.wait_group 1;" ::: "memory")

__device__ __forceinline__ void mma_tf32(float& c0, float& c1, float& c2, float& c3,
                                         uint32_t a0, uint32_t a1, uint32_t a2, uint32_t a3,
                                         uint32_t b0, uint32_t b1) {
    asm volatile(
        "mma.sync.aligned.m16n8k8.row.col.f32.tf32.tf32.f32 "
        "{%0,%1,%2,%3}, {%4,%5,%6,%7}, {%8,%9}, {%0,%1,%2,%3};"
        : "+f"(c0), "+f"(c1), "+f"(c2), "+f"(c3)
        : "r"(a0), "r"(a1), "r"(a2), "r"(a3), "r"(b0), "r"(b1));
}

__device__ __forceinline__ void cell_info(int j, int& sz, int& iy, int& ix) {
    if (j == 0)       { sz = 1; iy = 0; ix = 0; }
    else if (j < 5)   { sz = 2; int p = j - 1;  iy = p / 2; ix = p % 2; }
    else if (j < 14)  { sz = 3; int p = j - 5;  iy = p / 3; ix = p % 3; }
    else              { sz = 6; int p = j - 14; iy = p / 6; ix = p % 6; }
}

// ---------------- 1. adaptive pooling ----------------
__global__ void pool_kernel(const float* __restrict__ feats) {
    int nc = blockIdx.x;
    int n = nc / CIN;
    __shared__ float tile[HW];
    const float* src = feats + (size_t)nc * HW;
    for (int i = threadIdx.x; i < HW; i += blockDim.x) tile[i] = src[i];
    __syncthreads();
    int wid = threadIdx.x >> 5, lane = threadIdx.x & 31;
    int c = nc % CIN;
    for (int j = wid; j < NCELL; j += 8) {
        int sz, iy, ix; cell_info(j, sz, iy, ix);
        int hs = iy * H / sz, he = ((iy + 1) * H + sz - 1) / sz;
        int ws_ = ix * W / sz, we = ((ix + 1) * W + sz - 1) / sz;
        int ww = we - ws_;
        int cnt = (he - hs) * ww;
        float sum = 0.f;
        for (int t = lane; t < cnt; t += 32) {
            int r = hs + t / ww, col = ws_ + t % ww;
            sum += tile[r * W + col];
        }
        #pragma unroll
        for (int o = 16; o > 0; o >>= 1) sum += __shfl_xor_sync(0xffffffffu, sum, o);
        if (lane == 0) g_poolT[n][j][c] = sum / (float)cnt;
    }
}

// ---------------- 2. fused 1x1 conv + BN + leaky relu ----------------
__global__ void conv1x1bn_kernel(const float* __restrict__ w0, const float* __restrict__ w1,
                                 const float* __restrict__ w2, const float* __restrict__ w3,
                                 const float* __restrict__ g0, const float* __restrict__ b0,
                                 const float* __restrict__ g1, const float* __restrict__ b1,
                                 const float* __restrict__ g2, const float* __restrict__ b2,
                                 const float* __restrict__ g3, const float* __restrict__ b3) {
    int og = blockIdx.x, br = blockIdx.y;
    const float* wsrc = (br == 0) ? w0 : (br == 1) ? w1 : (br == 2) ? w2 : w3;
    const float* gam  = (br == 0) ? g0 : (br == 1) ? g1 : (br == 2) ? g2 : g3;
    const float* bet  = (br == 0) ? b0 : (br == 1) ? b1 : (br == 2) ? b2 : b3;
    int o0 = og * 4;
    __shared__ float sw[4][CIN];
    for (int i = threadIdx.x; i < 4 * CIN; i += 256)
        sw[i / CIN][i % CIN] = wsrc[(size_t)(o0 + i / CIN) * CIN + (i % CIN)];
    __syncthreads();
    int sz    = (br == 0) ? 1 : (br == 1) ? 2 : (br == 2) ? 3 : 6;
    int cell0 = (br == 0) ? 0 : (br == 1) ? 1 : (br == 2) ? 5 : 14;
    int pp = sz * sz;
    int np = N_IMG * pp;
    int wid = threadIdx.x >> 5, lane = threadIdx.x & 31;
    for (int j = wid; j < np; j += 8) {
        int n = j / pp, p = j % pp;
        const float* prow = &g_poolT[n][cell0 + p][0];
        float a0 = 0, a1 = 0, a2 = 0, a3 = 0;
        for (int k = lane; k < CIN; k += 32) {
            float v = prow[k];
            a0 += sw[0][k] * v; a1 += sw[1][k] * v;
            a2 += sw[2][k] * v; a3 += sw[3][k] * v;
        }
        #pragma unroll
        for (int o = 16; o > 0; o >>= 1) {
            a0 += __shfl_xor_sync(0xffffffffu, a0, o);
            a1 += __shfl_xor_sync(0xffffffffu, a1, o);
            a2 += __shfl_xor_sync(0xffffffffu, a2, o);
            a3 += __shfl_xor_sync(0xffffffffu, a3, o);
        }
        if (lane == 0) {
            g_prior[br][n][o0 + 0][p] = a0;
            g_prior[br][n][o0 + 1][p] = a1;
            g_prior[br][n][o0 + 2][p] = a2;
            g_prior[br][n][o0 + 3][p] = a3;
        }
    }
    __syncthreads();
    if (wid < 4) {
        int o = o0 + wid;
        int cnt = N_IMG * pp;
        float s = 0.f, sq = 0.f;
        for (int e = lane; e < cnt; e += 32) {
            float v = g_prior[br][e / pp][o][e % pp];
            s += v; sq += v * v;
        }
        #pragma unroll
        for (int k = 16; k > 0; k >>= 1) {
            s  += __shfl_xor_sync(0xffffffffu, s, k);
            sq += __shfl_xor_sync(0xffffffffu, sq, k);
        }
        float mean = s / (float)cnt;
        float var  = sq / (float)cnt - mean * mean;
        float sc = rsqrtf(var + EPSV) * gam[o];
        float sh = bet[o] - mean * sc;
        for (int e = lane; e < cnt; e += 32) {
            float v = g_prior[br][e / pp][o][e % pp];
            v = v * sc + sh;
            g_prior[br][e / pp][o][e % pp] = (v >= 0.f) ? v : SLOPE * v;
        }
    }
}

// ---------------- 3. fused prep ----------------
__global__ void __launch_bounds__(256) prep_kernel(const float* __restrict__ feats,
                                                   const float* __restrict__ wb) {
    __shared__ float sm[9472];
    int tid = threadIdx.x;
    int bid = blockIdx.x;

    if (bid < 4096) {
        int cc = bid & 15, xc = (bid >> 4) & 1, y = (bid >> 5) & 63, img = bid >> 11;
        int c0 = cc * 128, x0 = xc * 32;
        float (*t)[33] = (float(*)[33])sm;
        int cr = tid >> 5, xi = tid & 31;
        #pragma unroll
        for (int s = 0; s < 16; s++) {
            int c = cr + s * 8;
            t[c][xi] = feats[((size_t)(img * CIN + c0 + c)) * HW + y * W + x0 + xi];
        }
        __syncthreads();
        int w = tid >> 5, lane = tid & 31;
        #pragma unroll
        for (int s = 0; s < 4; s++) {
            int x = w + s * 8;
            float* dst = g_inp + ((size_t)(img * 66 + y + 1) * 66 + x0 + x + 1) * 2048 + c0;
            #pragma unroll
            for (int kk = 0; kk < 4; kk++)
                dst[lane + 32 * kk] = to_tf32(t[lane + 32 * kk][x]);
        }
    } else if (bid < 4616) {
        int q = bid - 4096;
        int img = q / 260, b = q % 260;
        int y, x;
        if (b < 66)       { y = 0;  x = b; }
        else if (b < 132) { y = 65; x = b - 66; }
        else if (b < 196) { y = b - 132 + 1; x = 0; }
        else              { y = b - 196 + 1; x = 65; }
        float* dst = g_inp + ((size_t)(img * 66 + y) * 66 + x) * 2048;
        for (int c = tid; c < 2048; c += 256) dst[c] = 0.f;
    } else if (bid < 6664) {
        int q = bid - 4616;
        int o = q >> 2, cg = q & 3, c0 = cg * 512;
        const float* src = wb + ((size_t)o * 4096 + 2048 + c0) * 9;
        for (int i = tid; i < 512 * 9; i += 256) sm[i] = src[i];
        __syncthreads();
        for (int tap = 0; tap < 9; tap++) {
            float* dst = g_wt + ((size_t)(tap * FOUT + o)) * 2048 + c0;
            for (int c = tid; c < 512; c += 256)
                dst[c] = to_tf32(sm[c * 9 + tap]);
        }
    } else if (bid < 6720) {
        int q = bid - 6664;
        int o0 = (q & 3) * 128;
        int gi = q >> 2;
        int br, cl0, nc;
        if (gi == 0)      { br = 0; cl0 = 0; nc = 1; }
        else if (gi == 1) { br = 1; cl0 = 0; nc = 4; }
        else if (gi < 5)  { br = 2; cl0 = (gi - 2) * 3; nc = 3; }
        else              { br = 3; cl0 = (gi - 5) * 4; nc = 4; }
        int cellg0 = (br == 0) ? 0 : (br == 1) ? 1 : (br == 2) ? 5 : 14;
        float (*Wsh)[73] = (float(*)[73])sm;
        float* Psh = sm + 128 * 73;
        int o = tid & 127, img = tid >> 7;
        float acc[4][9];
        #pragma unroll
        for (int i = 0; i < 4; i++)
            #pragma unroll
            for (int j = 0; j < 9; j++) acc[i][j] = 0.f;
        for (int c0 = 0; c0 < 512; c0 += 8) {
            for (int i = tid; i < 128 * 72; i += 256) {
                int oi = i / 72, r = i % 72;
                Wsh[oi][r] = wb[((size_t)(o0 + oi) * 4096 + 512 * br + c0) * 9 + r];
            }
            if (tid < 64) {
                int ii = tid >> 5, rem = tid & 31;
                int ci = rem >> 2, cl = rem & 3;
                if (cl < nc)
                    Psh[(ii * 8 + ci) * 4 + cl] = g_prior[br][ii][c0 + ci][cl0 + cl];
            }
            __syncthreads();
            #pragma unroll
            for (int cc = 0; cc < 8; cc++) {
                float pv[4];
                #pragma unroll
                for (int cl = 0; cl < 4; cl++) pv[cl] = Psh[(img * 8 + cc) * 4 + cl];
                #pragma unroll
                for (int tap = 0; tap < 9; tap++) {
                    float wv = Wsh[o][cc * 9 + tap];
                    #pragma unroll
                    for (int cl = 0; cl < 4; cl++) acc[cl][tap] += wv * pv[cl];
                }
            }
            __syncthreads();
        }
        for (int cl = 0; cl < nc; cl++)
            #pragma unroll
            for (int tap = 0; tap < 9; tap++)
                g_qa[img][o0 + o][(cellg0 + cl0 + cl) * 9 + tap] = to_tf32(acc[cl][tap]);
        if (gi == 0) {
            for (int kk = 450; kk < 480; kk++) g_qa[img][o0 + o][kk] = 0.f;
        }
    } else {
        int q = bid - 6720;
        int pix = q & 4095, img = q >> 12;
        int y = pix >> 6, x = pix & 63;
        float* dst = &g_lam[img][pix][0];
        for (int i = tid; i < 480; i += 256) dst[i] = 0.f;
        __syncthreads();
        if (tid < 36) {
            int br = tid / 9, tap = tid % 9;
            int ky = tap / 3, kx = tap % 3;
            int yp = y + ky - 1, xp = x + kx - 1;
            if (yp >= 0 && yp < 64 && xp >= 0 && xp < 64) {
                int sz = (br == 0) ? 1 : (br == 1) ? 2 : (br == 2) ? 3 : 6;
                int cellg0 = (br == 0) ? 0 : (br == 1) ? 1 : (br == 2) ? 5 : 14;
                float scale = (float)(sz - 1) / 63.f;
                float yc = yp * scale, xc = xp * scale;
                int y0 = (int)floorf(yc), x0 = (int)floorf(xc);
                int y1 = min(y0 + 1, sz - 1), x1 = min(x0 + 1, sz - 1);
                float wy = yc - (float)y0, wx = xc - (float)x0;
                int ys[2] = {y0, y1}; float wys[2] = {1.f - wy, wy};
                int ny = 2;
                if (y1 == y0) { wys[0] += wys[1]; ny = 1; }
                int xs[2] = {x0, x1}; float wxs[2] = {1.f - wx, wx};
                int nx = 2;
                if (x1 == x0) { wxs[0] += wxs[1]; nx = 1; }
                for (int iy = 0; iy < ny; iy++)
                    for (int ix = 0; ix < nx; ix++) {
                        int k = (cellg0 + ys[iy] * sz + xs[ix]) * 9 + tap;
                        dst[k] = to_tf32(wys[iy] * wxs[ix]);
                    }
            }
        }
    }
}

// ---------------- 4. mma.sync tf32 GEMM (128x128 tile, 2 CTAs/SM, 3-stage) ----------------
#define NKF 576
#define NK  591
#define A_STG 4608
#define B_STG 4608
#define STG   9216
#define GEMM_SMEM (3 * STG * 4)

__global__ void __launch_bounds__(256, 2) gemm_kernel() {
    extern __shared__ __align__(16) float smem[];
    int tid = threadIdx.x;
    int lane = tid & 31, wid = tid >> 5;
    int n_tile = blockIdx.x;            // 0..63
    int m_tile = blockIdx.y;            // 0..3
    int img = n_tile >> 5;
    int rb  = n_tile & 31;
    int y0 = rb * 2, pix0 = rb * 128;
    int oc0 = m_tile * 128;

    int wm = wid & 3, wn = wid >> 2;    // 4(m) x 2(n)
    int m0 = wm * 32, n0 = wn * 64;
    int g = lane >> 2, cq = lane & 3;

    uint32_t sbase = smem_u32(smem);
    int ar = tid >> 3, aq = tid & 7;    // A rows ar+32j (j<4)

    int pb0, pb1, pb2, pb3;
    int lb0, lb1, lb2, lb3;
    {
        int n, rr, x;
        n = tid >> 3;          rr = n >> 6; x = n & 63; pb0 = (rr * 66 + x) * 2048; lb0 = ((y0 + rr) * 64 + x) * 480;
        n = (tid + 256) >> 3;  rr = n >> 6; x = n & 63; pb1 = (rr * 66 + x) * 2048; lb1 = ((y0 + rr) * 64 + x) * 480;
        n = (tid + 512) >> 3;  rr = n >> 6; x = n & 63; pb2 = (rr * 66 + x) * 2048; lb2 = ((y0 + rr) * 64 + x) * 480;
        n = (tid + 768) >> 3;  rr = n >> 6; x = n & 63; pb3 = (rr * 66 + x) * 2048; lb3 = ((y0 + rr) * 64 + x) * 480;
    }
    const float* inp_base = g_inp + (size_t)((img * 66 + y0) * 66) * 2048 + aq * 4;
    const float* lam_base = &g_lam[img][0][0] + aq * 4;

    float acc[2][8][4];
    #pragma unroll
    for (int mt = 0; mt < 2; mt++)
        #pragma unroll
        for (int nt = 0; nt < 8; nt++)
            #pragma unroll
            for (int e = 0; e < 4; e++) acc[mt][nt][e] = 0.f;

    uint32_t sa_a = sbase + (uint32_t)(ar * 144 + aq * 16);
    uint32_t sa_b0 = sbase + A_STG * 4 + (uint32_t)((tid >> 3) * 144 + aq * 16);
    uint32_t sa_b1 = sbase + A_STG * 4 + (uint32_t)((((tid + 256) >> 3)) * 144 + aq * 16);
    uint32_t sa_b2 = sbase + A_STG * 4 + (uint32_t)((((tid + 512) >> 3)) * 144 + aq * 16);
    uint32_t sa_b3 = sbase + A_STG * 4 + (uint32_t)((((tid + 768) >> 3)) * 144 + aq * 16);

    auto load_chunk = [&](int k, int s) {
        uint32_t soff = (uint32_t)s * (STG * 4);
        if (k < NKF) {
            int tap = k >> 6;
            int c0 = (k & 63) << 5;
            int ky = tap / 3, kx = tap - ky * 3;
            const float* wsrc = g_wt + (size_t)(tap * 512 + oc0 + ar) * 2048 + c0 + aq * 4;
            #pragma unroll
            for (int j = 0; j < 4; j++)
                cp16(sa_a + soff + j * (32 * 144), wsrc + j * (32 * 2048));
            const float* bsrc = inp_base + (ky * 66 + kx) * 2048 + c0;
            cp16(sa_b0 + soff, bsrc + pb0);
            cp16(sa_b1 + soff, bsrc + pb1);
            cp16(sa_b2 + soff, bsrc + pb2);
            cp16(sa_b3 + soff, bsrc + pb3);
        } else {
            int kk = (k - NKF) << 5;
            const float* qsrc = &g_qa[img][oc0 + ar][kk] + aq * 4;
            #pragma unroll
            for (int j = 0; j < 4; j++)
                cp16(sa_a + soff + j * (32 * 144), qsrc + j * (32 * 480));
            const float* lsrc = lam_base + kk;
            cp16(sa_b0 + soff, lsrc + lb0);
            cp16(sa_b1 + soff, lsrc + lb1);
            cp16(sa_b2 + soff, lsrc + lb2);
            cp16(sa_b3 + soff, lsrc + lb3);
        }
        CP_COMMIT();
    };

    load_chunk(0, 0);
    load_chunk(1, 1);

    int scomp = 0, sload = 2;
    for (int k = 0; k < NK; k++) {
        CP_WAIT1();
        __syncthreads();
        if (k + 2 < NK) load_chunk(k + 2, sload);
        else            CP_COMMIT();

        const float* sA = smem + scomp * STG;
        const float* sB = sA + A_STG;
        #pragma unroll
        for (int k8 = 0; k8 < 4; k8++) {
            int k0 = k8 * 8;
            uint32_t a[2][4], b[8][2];
            #pragma unroll
            for (int mt = 0; mt < 2; mt++) {
                int row = m0 + mt * 16 + g;
                a[mt][0] = __float_as_uint(sA[row * 36 + k0 + cq]);
                a[mt][1] = __float_as_uint(sA[(row + 8) * 36 + k0 + cq]);
                a[mt][2] = __float_as_uint(sA[row * 36 + k0 + cq + 4]);
                a[mt][3] = __float_as_uint(sA[(row + 8) * 36 + k0 + cq + 4]);
            }
            #pragma unroll
            for (int nt = 0; nt < 8; nt++) {
                int col = n0 + nt * 8 + g;
                b[nt][0] = __float_as_uint(sB[col * 36 + k0 + cq]);
                b[nt][1] = __float_as_uint(sB[col * 36 + k0 + cq + 4]);
            }
            #pragma unroll
            for (int mt = 0; mt < 2; mt++)
                #pragma unroll
                for (int nt = 0; nt < 8; nt++)
                    mma_tf32(acc[mt][nt][0], acc[mt][nt][1], acc[mt][nt][2], acc[mt][nt][3],
                             a[mt][0], a[mt][1], a[mt][2], a[mt][3], b[nt][0], b[nt][1]);
        }
        scomp++; if (scomp == 3) scomp = 0;
        sload++; if (sload == 3) sload = 0;
    }

    #pragma unroll
    for (int mt = 0; mt < 2; mt++) {
        int row = m0 + mt * 16 + g;
        #pragma unroll
        for (int nt = 0; nt < 8; nt++) {
            int col = pix0 + n0 + nt * 8 + 2 * cq;
            *(float2*)&g_conv[img][oc0 + row][col]     = make_float2(acc[mt][nt][0], acc[mt][nt][1]);
            *(float2*)&g_conv[img][oc0 + row + 8][col] = make_float2(acc[mt][nt][2], acc[mt][nt][3]);
        }
    }
}

// ---------------- 5. final BN stats ----------------
__global__ void out_stats_kernel() {
    int c = blockIdx.x, tid = threadIdx.x;
    float s = 0.f, sq = 0.f;
    for (int e = tid; e < N_IMG * HW; e += 256) {
        float v = g_conv[e / HW][c][e % HW];
        s += v; sq += v * v;
    }
    __shared__ float shs[8], shq[8];
    #pragma unroll
    for (int k = 16; k > 0; k >>= 1) {
        s  += __shfl_xor_sync(0xffffffffu, s, k);
        sq += __shfl_xor_sync(0xffffffffu, sq, k);
    }
    if ((tid & 31) == 0) { shs[tid >> 5] = s; shq[tid >> 5] = sq; }
    __syncthreads();
    if (tid == 0) {
        float ts = 0.f, tq = 0.f;
        #pragma unroll
        for (int k = 0; k < 8; k++) { ts += shs[k]; tq += shq[k]; }
        float mean = ts / (float)(N_IMG * HW);
        float var  = tq / (float)(N_IMG * HW) - mean * mean;
        g_ostat[c][0] = mean;
        g_ostat[c][1] = var;
    }
}

// ---------------- 6. finalize: BN + leaky relu ----------------
__global__ void finalize_kernel(const float* __restrict__ gb, const float* __restrict__ bb,
                                float* __restrict__ out) {
    int idx = blockIdx.x * 256 + threadIdx.x;
    if (idx >= N_IMG * FOUT * HW) return;
    int c = (idx >> 12) & 511;
    float mean = g_ostat[c][0], var = g_ostat[c][1];
    float sc = rsqrtf(var + EPSV) * gb[c];
    float v = ((const float*)g_conv)[idx];
    v = (v - mean) * sc + bb[c];
    out[idx] = (v >= 0.f) ? v : SLOPE * v;
}

// ---------------- launch ----------------
extern "C" void kernel_launch(void* const* d_in, const int* in_sizes, int n_in,
                              void* d_out, int out_size) {
    const float* feats = (const float*)d_in[0];
    const float* w0 = (const float*)d_in[1];
    const float* g0 = (const float*)d_in[2];
    const float* b0 = (const float*)d_in[3];
    const float* w1 = (const float*)d_in[4];
    const float* g1 = (const float*)d_in[5];
    const float* b1 = (const float*)d_in[6];
    const float* w2 = (const float*)d_in[7];
    const float* g2 = (const float*)d_in[8];
    const float* b2 = (const float*)d_in[9];
    const float* w3 = (const float*)d_in[10];
    const float* g3 = (const float*)d_in[11];
    const float* b3 = (const float*)d_in[12];
    const float* wb = (const float*)d_in[13];
    const float* gb = (const float*)d_in[14];
    const float* bb = (const float*)d_in[15];

    static int smem_set = 0;
    if (!smem_set) {
        cudaFuncSetAttribute(gemm_kernel, cudaFuncAttributeMaxDynamicSharedMemorySize, GEMM_SMEM);
        smem_set = 1;
    }

    pool_kernel<<<N_IMG * CIN, 256>>>(feats);                                   // 0
    conv1x1bn_kernel<<<dim3(128, 4), 256>>>(w0, w1, w2, w3,
                                            g0, b0, g1, b1, g2, b2, g3, b3);    // 1
    prep_kernel<<<14912, 256>>>(feats, wb);                                     // 2
    gemm_kernel<<<dim3(64, 4), 256, GEMM_SMEM>>>();                             // 3 (ncu target)
    out_stats_kernel<<<FOUT, 256>>>();                                          // 4
    finalize_kernel<<<(N_IMG * FOUT * HW) / 256, 256>>>(gb, bb, (float*)d_out); // 5
}

// round 11
// speedup vs baseline: 1.8854x; 1.8854x over previous
#include <cuda_runtime.h>
#include <cuda_fp16.h>
#include <cstdint>

#define N_IMG 2
#define CIN   2048
#define FOUT  512
#define H     64
#define W     64
#define HW    4096
#define NCELL 50
#define EPSV  1e-5f
#define SLOPE 0.01f

// ---------------- device scratch ----------------
__device__ float  g_poolT[N_IMG][NCELL][CIN];
__device__ float  g_prior[4][N_IMG][FOUT][36];
__device__ __half g_inp[(size_t)N_IMG * 66 * 66 * 2048];   // NHWC padded feats (fp16)
__device__ __half g_wt[(size_t)9 * FOUT * 2048];           // feats weights [tap][o][c] (fp16)
__device__ __half g_qa[N_IMG][FOUT][480];                  // prior-collapsed A (fp16)
__device__ __half g_lam[N_IMG][HW][480];                   // geometric weights (fp16)
__device__ float  g_conv[N_IMG][FOUT][HW];
__device__ float  g_ostat[FOUT][2];

__device__ __forceinline__ uint32_t smem_u32(const void* p) {
    uint32_t a;
    asm("{ .reg .u64 t; cvta.to.shared.u64 t, %1; cvt.u32.u64 %0, t; }" : "=r"(a) : "l"(p));
    return a;
}
__device__ __forceinline__ void cp16(uint32_t saddr, const void* gaddr) {
    asm volatile("cp.async.cg.shared.global [%0], [%1], 16;" :: "r"(saddr), "l"(gaddr));
}
#define CP_COMMIT() asm volatile("cp.async.commit_group;" ::: "memory")
#define CP_WAIT1()  asm volatile("cp.async.wait_group 1;" ::: "memory")

__device__ __forceinline__ void mma_f16(float& c0, float& c1, float& c2, float& c3,
                                        uint32_t a0, uint32_t a1, uint32_t a2, uint32_t a3,
                                        uint32_t b0, uint32_t b1) {
    asm volatile(
        "mma.sync.aligned.m16n8k16.row.col.f32.f16.f16.f32 "
        "{%0,%1,%2,%3}, {%4,%5,%6,%7}, {%8,%9}, {%0,%1,%2,%3};"
        : "+f"(c0), "+f"(c1), "+f"(c2), "+f"(c3)
        : "r"(a0), "r"(a1), "r"(a2), "r"(a3), "r"(b0), "r"(b1));
}

__device__ __forceinline__ void cell_info(int j, int& sz, int& iy, int& ix) {
    if (j == 0)       { sz = 1; iy = 0; ix = 0; }
    else if (j < 5)   { sz = 2; int p = j - 1;  iy = p / 2; ix = p % 2; }
    else if (j < 14)  { sz = 3; int p = j - 5;  iy = p / 3; ix = p % 3; }
    else              { sz = 6; int p = j - 14; iy = p / 6; ix = p % 6; }
}

// ---------------- 1. adaptive pooling ----------------
__global__ void pool_kernel(const float* __restrict__ feats) {
    int nc = blockIdx.x;
    int n = nc / CIN;
    __shared__ float tile[HW];
    const float* src = feats + (size_t)nc * HW;
    for (int i = threadIdx.x; i < HW; i += blockDim.x) tile[i] = src[i];
    __syncthreads();
    int wid = threadIdx.x >> 5, lane = threadIdx.x & 31;
    int c = nc % CIN;
    for (int j = wid; j < NCELL; j += 8) {
        int sz, iy, ix; cell_info(j, sz, iy, ix);
        int hs = iy * H / sz, he = ((iy + 1) * H + sz - 1) / sz;
        int ws_ = ix * W / sz, we = ((ix + 1) * W + sz - 1) / sz;
        int ww = we - ws_;
        int cnt = (he - hs) * ww;
        float sum = 0.f;
        for (int t = lane; t < cnt; t += 32) {
            int r = hs + t / ww, col = ws_ + t % ww;
            sum += tile[r * W + col];
        }
        #pragma unroll
        for (int o = 16; o > 0; o >>= 1) sum += __shfl_xor_sync(0xffffffffu, sum, o);
        if (lane == 0) g_poolT[n][j][c] = sum / (float)cnt;
    }
}

// ---------------- 2. fused 1x1 conv + BN + leaky relu ----------------
__global__ void conv1x1bn_kernel(const float* __restrict__ w0, const float* __restrict__ w1,
                                 const float* __restrict__ w2, const float* __restrict__ w3,
                                 const float* __restrict__ g0, const float* __restrict__ b0,
                                 const float* __restrict__ g1, const float* __restrict__ b1,
                                 const float* __restrict__ g2, const float* __restrict__ b2,
                                 const float* __restrict__ g3, const float* __restrict__ b3) {
    int og = blockIdx.x, br = blockIdx.y;
    const float* wsrc = (br == 0) ? w0 : (br == 1) ? w1 : (br == 2) ? w2 : w3;
    const float* gam  = (br == 0) ? g0 : (br == 1) ? g1 : (br == 2) ? g2 : g3;
    const float* bet  = (br == 0) ? b0 : (br == 1) ? b1 : (br == 2) ? b2 : b3;
    int o0 = og * 4;
    __shared__ float sw[4][CIN];
    for (int i = threadIdx.x; i < 4 * CIN; i += 256)
        sw[i / CIN][i % CIN] = wsrc[(size_t)(o0 + i / CIN) * CIN + (i % CIN)];
    __syncthreads();
    int sz    = (br == 0) ? 1 : (br == 1) ? 2 : (br == 2) ? 3 : 6;
    int cell0 = (br == 0) ? 0 : (br == 1) ? 1 : (br == 2) ? 5 : 14;
    int pp = sz * sz;
    int np = N_IMG * pp;
    int wid = threadIdx.x >> 5, lane = threadIdx.x & 31;
    for (int j = wid; j < np; j += 8) {
        int n = j / pp, p = j % pp;
        const float* prow = &g_poolT[n][cell0 + p][0];
        float a0 = 0, a1 = 0, a2 = 0, a3 = 0;
        for (int k = lane; k < CIN; k += 32) {
            float v = prow[k];
            a0 += sw[0][k] * v; a1 += sw[1][k] * v;
            a2 += sw[2][k] * v; a3 += sw[3][k] * v;
        }
        #pragma unroll
        for (int o = 16; o > 0; o >>= 1) {
            a0 += __shfl_xor_sync(0xffffffffu, a0, o);
            a1 += __shfl_xor_sync(0xffffffffu, a1, o);
            a2 += __shfl_xor_sync(0xffffffffu, a2, o);
            a3 += __shfl_xor_sync(0xffffffffu, a3, o);
        }
        if (lane == 0) {
            g_prior[br][n][o0 + 0][p] = a0;
            g_prior[br][n][o0 + 1][p] = a1;
            g_prior[br][n][o0 + 2][p] = a2;
            g_prior[br][n][o0 + 3][p] = a3;
        }
    }
    __syncthreads();
    if (wid < 4) {
        int o = o0 + wid;
        int cnt = N_IMG * pp;
        float s = 0.f, sq = 0.f;
        for (int e = lane; e < cnt; e += 32) {
            float v = g_prior[br][e / pp][o][e % pp];
            s += v; sq += v * v;
        }
        #pragma unroll
        for (int k = 16; k > 0; k >>= 1) {
            s  += __shfl_xor_sync(0xffffffffu, s, k);
            sq += __shfl_xor_sync(0xffffffffu, sq, k);
        }
        float mean = s / (float)cnt;
        float var  = sq / (float)cnt - mean * mean;
        float sc = rsqrtf(var + EPSV) * gam[o];
        float sh = bet[o] - mean * sc;
        for (int e = lane; e < cnt; e += 32) {
            float v = g_prior[br][e / pp][o][e % pp];
            v = v * sc + sh;
            g_prior[br][e / pp][o][e % pp] = (v >= 0.f) ? v : SLOPE * v;
        }
    }
}

// ---------------- 3. fused prep (fp16 outputs) ----------------
__global__ void __launch_bounds__(256) prep_kernel(const float* __restrict__ feats,
                                                   const float* __restrict__ wb) {
    __shared__ float sm[9472];
    int tid = threadIdx.x;
    int bid = blockIdx.x;

    if (bid < 4096) {
        int cc = bid & 15, xc = (bid >> 4) & 1, y = (bid >> 5) & 63, img = bid >> 11;
        int c0 = cc * 128, x0 = xc * 32;
        float (*t)[33] = (float(*)[33])sm;
        int cr = tid >> 5, xi = tid & 31;
        #pragma unroll
        for (int s = 0; s < 16; s++) {
            int c = cr + s * 8;
            t[c][xi] = feats[((size_t)(img * CIN + c0 + c)) * HW + y * W + x0 + xi];
        }
        __syncthreads();
        int w = tid >> 5, lane = tid & 31;
        #pragma unroll
        for (int s = 0; s < 4; s++) {
            int x = w + s * 8;
            __half* dst = g_inp + ((size_t)(img * 66 + y + 1) * 66 + x0 + x + 1) * 2048 + c0;
            #pragma unroll
            for (int kk = 0; kk < 4; kk++)
                dst[lane + 32 * kk] = __float2half_rn(t[lane + 32 * kk][x]);
        }
    } else if (bid < 4616) {
        int q = bid - 4096;
        int img = q / 260, b = q % 260;
        int y, x;
        if (b < 66)       { y = 0;  x = b; }
        else if (b < 132) { y = 65; x = b - 66; }
        else if (b < 196) { y = b - 132 + 1; x = 0; }
        else              { y = b - 196 + 1; x = 65; }
        uint32_t* dst = (uint32_t*)(g_inp + ((size_t)(img * 66 + y) * 66 + x) * 2048);
        for (int c = tid; c < 1024; c += 256) dst[c] = 0u;
    } else if (bid < 6664) {
        int q = bid - 4616;
        int o = q >> 2, cg = q & 3, c0 = cg * 512;
        const float* src = wb + ((size_t)o * 4096 + 2048 + c0) * 9;
        for (int i = tid; i < 512 * 9; i += 256) sm[i] = src[i];
        __syncthreads();
        for (int tap = 0; tap < 9; tap++) {
            __half* dst = g_wt + ((size_t)(tap * FOUT + o)) * 2048 + c0;
            for (int c = tid; c < 512; c += 256)
                dst[c] = __float2half_rn(sm[c * 9 + tap]);
        }
    } else if (bid < 6720) {
        int q = bid - 6664;
        int o0 = (q & 3) * 128;
        int gi = q >> 2;
        int br, cl0, nc;
        if (gi == 0)      { br = 0; cl0 = 0; nc = 1; }
        else if (gi == 1) { br = 1; cl0 = 0; nc = 4; }
        else if (gi < 5)  { br = 2; cl0 = (gi - 2) * 3; nc = 3; }
        else              { br = 3; cl0 = (gi - 5) * 4; nc = 4; }
        int cellg0 = (br == 0) ? 0 : (br == 1) ? 1 : (br == 2) ? 5 : 14;
        float (*Wsh)[73] = (float(*)[73])sm;
        float* Psh = sm + 128 * 73;
        int o = tid & 127, img = tid >> 7;
        float acc[4][9];
        #pragma unroll
        for (int i = 0; i < 4; i++)
            #pragma unroll
            for (int j = 0; j < 9; j++) acc[i][j] = 0.f;
        for (int c0 = 0; c0 < 512; c0 += 8) {
            for (int i = tid; i < 128 * 72; i += 256) {
                int oi = i / 72, r = i % 72;
                Wsh[oi][r] = wb[((size_t)(o0 + oi) * 4096 + 512 * br + c0) * 9 + r];
            }
            if (tid < 64) {
                int ii = tid >> 5, rem = tid & 31;
                int ci = rem >> 2, cl = rem & 3;
                if (cl < nc)
                    Psh[(ii * 8 + ci) * 4 + cl] = g_prior[br][ii][c0 + ci][cl0 + cl];
            }
            __syncthreads();
            #pragma unroll
            for (int cc = 0; cc < 8; cc++) {
                float pv[4];
                #pragma unroll
                for (int cl = 0; cl < 4; cl++) pv[cl] = Psh[(img * 8 + cc) * 4 + cl];
                #pragma unroll
                for (int tap = 0; tap < 9; tap++) {
                    float wv = Wsh[o][cc * 9 + tap];
                    #pragma unroll
                    for (int cl = 0; cl < 4; cl++) acc[cl][tap] += wv * pv[cl];
                }
            }
            __syncthreads();
        }
        for (int cl = 0; cl < nc; cl++)
            #pragma unroll
            for (int tap = 0; tap < 9; tap++)
                g_qa[img][o0 + o][(cellg0 + cl0 + cl) * 9 + tap] = __float2half_rn(acc[cl][tap]);
        if (gi == 0) {
            for (int kk = 450; kk < 480; kk++) g_qa[img][o0 + o][kk] = __float2half_rn(0.f);
        }
    } else {
        int q = bid - 6720;
        int pix = q & 4095, img = q >> 12;
        int y = pix >> 6, x = pix & 63;
        __half* dst = &g_lam[img][pix][0];
        for (int i = tid; i < 240; i += 256) ((uint32_t*)dst)[i] = 0u;
        __syncthreads();
        if (tid < 36) {
            int br = tid / 9, tap = tid % 9;
            int ky = tap / 3, kx = tap % 3;
            int yp = y + ky - 1, xp = x + kx - 1;
            if (yp >= 0 && yp < 64 && xp >= 0 && xp < 64) {
                int sz = (br == 0) ? 1 : (br == 1) ? 2 : (br == 2) ? 3 : 6;
                int cellg0 = (br == 0) ? 0 : (br == 1) ? 1 : (br == 2) ? 5 : 14;
                float scale = (float)(sz - 1) / 63.f;
                float yc = yp * scale, xc = xp * scale;
                int y0 = (int)floorf(yc), x0 = (int)floorf(xc);
                int y1 = min(y0 + 1, sz - 1), x1 = min(x0 + 1, sz - 1);
                float wy = yc - (float)y0, wx = xc - (float)x0;
                int ys[2] = {y0, y1}; float wys[2] = {1.f - wy, wy};
                int ny = 2;
                if (y1 == y0) { wys[0] += wys[1]; ny = 1; }
                int xs[2] = {x0, x1}; float wxs[2] = {1.f - wx, wx};
                int nx = 2;
                if (x1 == x0) { wxs[0] += wxs[1]; nx = 1; }
                for (int iy = 0; iy < ny; iy++)
                    for (int ix = 0; ix < nx; ix++) {
                        int k = (cellg0 + ys[iy] * sz + xs[ix]) * 9 + tap;
                        dst[k] = __float2half_rn(wys[iy] * wxs[ix]);
                    }
            }
        }
    }
}

// ---------------- 4. mma.sync fp16 GEMM (256x128 tile, 3-stage) ----------------
// smem rows padded: K-chunk 32 halfs (64B) + 16B pad = 80B pitch.
#define NKF 576
#define NK  591
#define PITCHB 80
#define A_STG_B (256 * PITCHB)          // 20480 B
#define B_STG_B (128 * PITCHB)          // 10240 B
#define STG_B   (A_STG_B + B_STG_B)     // 30720 B
#define GEMM_SMEM (3 * STG_B)

__global__ void __launch_bounds__(256, 1) gemm_kernel() {
    extern __shared__ __align__(16) char smemc[];
    __half* smem = (__half*)smemc;
    int tid = threadIdx.x;
    int lane = tid & 31, wid = tid >> 5;
    int n_tile = blockIdx.x;            // 0..63
    int m_tile = blockIdx.y;            // 0..1
    int img = n_tile >> 5;
    int rb  = n_tile & 31;
    int y0 = rb * 2, pix0 = rb * 128;
    int oc0 = m_tile * 256;

    int wm = wid & 3, wn = wid >> 2;    // 4(m) x 2(n)
    int m0 = wm * 64, n0 = wn * 64;
    int g = lane >> 2, cq = lane & 3;

    uint32_t sbase = smem_u32(smem);
    int arow = tid >> 2, aseg = tid & 3;    // A: 1024 ops, row = idx>>2, seg = idx&3

    // B pixel offsets for the 2 ops (idx = tid, tid+256): n = idx>>2
    int pb0, pb1, lb0, lb1;
    {
        int n, rr, x;
        n = tid >> 2;         rr = n >> 6; x = n & 63; pb0 = (rr * 66 + x) * 2048; lb0 = ((y0 + rr) * 64 + x) * 480;
        n = (tid + 256) >> 2; rr = n >> 6; x = n & 63; pb1 = (rr * 66 + x) * 2048; lb1 = ((y0 + rr) * 64 + x) * 480;
    }
    const __half* inp_base = g_inp + (size_t)((img * 66 + y0) * 66) * 2048 + aseg * 8;
    const __half* lam_base = &g_lam[img][0][0] + aseg * 8;

    float acc[4][8][4];
    #pragma unroll
    for (int mt = 0; mt < 4; mt++)
        #pragma unroll
        for (int nt = 0; nt < 8; nt++)
            #pragma unroll
            for (int e = 0; e < 4; e++) acc[mt][nt][e] = 0.f;

    uint32_t sa_a  = sbase + (uint32_t)(arow * PITCHB + aseg * 16);
    uint32_t sa_b0 = sbase + A_STG_B + (uint32_t)((tid >> 2) * PITCHB + aseg * 16);
    uint32_t sa_b1 = sbase + A_STG_B + (uint32_t)(((tid + 256) >> 2) * PITCHB + aseg * 16);

    auto load_chunk = [&](int k, int s) {
        uint32_t soff = (uint32_t)s * STG_B;
        if (k < NKF) {
            int tap = k >> 6;
            int c0 = (k & 63) << 5;
            int ky = tap / 3, kx = tap - ky * 3;
            const __half* wsrc = g_wt + (size_t)(tap * 512 + oc0 + arow) * 2048 + c0 + aseg * 8;
            #pragma unroll
            for (int j = 0; j < 4; j++)
                cp16(sa_a + soff + j * (64 * PITCHB), wsrc + j * (size_t)(64 * 2048));
            const __half* bsrc = inp_base + (ky * 66 + kx) * 2048 + c0;
            cp16(sa_b0 + soff, bsrc + pb0);
            cp16(sa_b1 + soff, bsrc + pb1);
        } else {
            int kk = (k - NKF) << 5;
            const __half* qsrc = &g_qa[img][oc0 + arow][kk] + aseg * 8;
            #pragma unroll
            for (int j = 0; j < 4; j++)
                cp16(sa_a + soff + j * (64 * PITCHB), qsrc + j * (size_t)(64 * 480));
            const __half* lsrc = lam_base + kk;
            cp16(sa_b0 + soff, lsrc + lb0);
            cp16(sa_b1 + soff, lsrc + lb1);
        }
        CP_COMMIT();
    };

    load_chunk(0, 0);
    load_chunk(1, 1);

    int scomp = 0, sload = 2;
    for (int k = 0; k < NK; k++) {
        CP_WAIT1();
        __syncthreads();
        if (k + 2 < NK) load_chunk(k + 2, sload);
        else            CP_COMMIT();

        const __half* sA = smem + scomp * (STG_B / 2);
        const __half* sB = sA + (A_STG_B / 2);
        #pragma unroll
        for (int k8 = 0; k8 < 2; k8++) {
            // byte offset of k within a row: k0*2 ; k0 = k8*16
            int kb = k8 * 32 + cq * 4;
            uint32_t a[4][4], b[8][2];
            #pragma unroll
            for (int mt = 0; mt < 4; mt++) {
                int row = m0 + mt * 16 + g;
                const char* base = (const char*)sA + row * PITCHB + kb;
                a[mt][0] = *(const uint32_t*)(base);
                a[mt][2] = *(const uint32_t*)(base + 16);
                const char* base8 = (const char*)sA + (row + 8) * PITCHB + kb;
                a[mt][1] = *(const uint32_t*)(base8);
                a[mt][3] = *(const uint32_t*)(base8 + 16);
            }
            #pragma unroll
            for (int nt = 0; nt < 8; nt++) {
                int col = n0 + nt * 8 + g;
                const char* base = (const char*)sB + col * PITCHB + kb;
                b[nt][0] = *(const uint32_t*)(base);
                b[nt][1] = *(const uint32_t*)(base + 16);
            }
            #pragma unroll
            for (int mt = 0; mt < 4; mt++)
                #pragma unroll
                for (int nt = 0; nt < 8; nt++)
                    mma_f16(acc[mt][nt][0], acc[mt][nt][1], acc[mt][nt][2], acc[mt][nt][3],
                            a[mt][0], a[mt][1], a[mt][2], a[mt][3], b[nt][0], b[nt][1]);
        }
        scomp++; if (scomp == 3) scomp = 0;
        sload++; if (sload == 3) sload = 0;
    }

    #pragma unroll
    for (int mt = 0; mt < 4; mt++) {
        int row = m0 + mt * 16 + g;
        #pragma unroll
        for (int nt = 0; nt < 8; nt++) {
            int col = pix0 + n0 + nt * 8 + 2 * cq;
            *(float2*)&g_conv[img][oc0 + row][col]     = make_float2(acc[mt][nt][0], acc[mt][nt][1]);
            *(float2*)&g_conv[img][oc0 + row + 8][col] = make_float2(acc[mt][nt][2], acc[mt][nt][3]);
        }
    }
}

// ---------------- 5. final BN stats ----------------
__global__ void out_stats_kernel() {
    int c = blockIdx.x, tid = threadIdx.x;
    float s = 0.f, sq = 0.f;
    for (int e = tid; e < N_IMG * HW; e += 256) {
        float v = g_conv[e / HW][c][e % HW];
        s += v; sq += v * v;
    }
    __shared__ float shs[8], shq[8];
    #pragma unroll
    for (int k = 16; k > 0; k >>= 1) {
        s  += __shfl_xor_sync(0xffffffffu, s, k);
        sq += __shfl_xor_sync(0xffffffffu, sq, k);
    }
    if ((tid & 31) == 0) { shs[tid >> 5] = s; shq[tid >> 5] = sq; }
    __syncthreads();
    if (tid == 0) {
        float ts = 0.f, tq = 0.f;
        #pragma unroll
        for (int k = 0; k < 8; k++) { ts += shs[k]; tq += shq[k]; }
        float mean = ts / (float)(N_IMG * HW);
        float var  = tq / (float)(N_IMG * HW) - mean * mean;
        g_ostat[c][0] = mean;
        g_ostat[c][1] = var;
    }
}

// ---------------- 6. finalize: BN + leaky relu ----------------
__global__ void finalize_kernel(const float* __restrict__ gb, const float* __restrict__ bb,
                                float* __restrict__ out) {
    int idx = blockIdx.x * 256 + threadIdx.x;
    if (idx >= N_IMG * FOUT * HW) return;
    int c = (idx >> 12) & 511;
    float mean = g_ostat[c][0], var = g_ostat[c][1];
    float sc = rsqrtf(var + EPSV) * gb[c];
    float v = ((const float*)g_conv)[idx];
    v = (v - mean) * sc + bb[c];
    out[idx] = (v >= 0.f) ? v : SLOPE * v;
}

// ---------------- launch ----------------
extern "C" void kernel_launch(void* const* d_in, const int* in_sizes, int n_in,
                              void* d_out, int out_size) {
    const float* feats = (const float*)d_in[0];
    const float* w0 = (const float*)d_in[1];
    const float* g0 = (const float*)d_in[2];
    const float* b0 = (const float*)d_in[3];
    const float* w1 = (const float*)d_in[4];
    const float* g1 = (const float*)d_in[5];
    const float* b1 = (const float*)d_in[6];
    const float* w2 = (const float*)d_in[7];
    const float* g2 = (const float*)d_in[8];
    const float* b2 = (const float*)d_in[9];
    const float* w3 = (const float*)d_in[10];
    const float* g3 = (const float*)d_in[11];
    const float* b3 = (const float*)d_in[12];
    const float* wb = (const float*)d_in[13];
    const float* gb = (const float*)d_in[14];
    const float* bb = (const float*)d_in[15];

    static int smem_set = 0;
    if (!smem_set) {
        cudaFuncSetAttribute(gemm_kernel, cudaFuncAttributeMaxDynamicSharedMemorySize, GEMM_SMEM);
        smem_set = 1;
    }

    pool_kernel<<<N_IMG * CIN, 256>>>(feats);                                   // 0
    conv1x1bn_kernel<<<dim3(128, 4), 256>>>(w0, w1, w2, w3,
                                            g0, b0, g1, b1, g2, b2, g3, b3);    // 1
    prep_kernel<<<14912, 256>>>(feats, wb);                                     // 2
    gemm_kernel<<<dim3(64, 2), 256, GEMM_SMEM>>>();                             // 3 (ncu target)
    out_stats_kernel<<<FOUT, 256>>>();                                          // 4
    finalize_kernel<<<(N_IMG * FOUT * HW) / 256, 256>>>(gb, bb, (float*)d_out); // 5
}

// round 14
// speedup vs baseline: 1.9280x; 1.0225x over previous
#include <cuda_runtime.h>
#include <cuda_fp16.h>
#include <cstdint>

#define N_IMG 2
#define CIN   2048
#define FOUT  512
#define H     64
#define W     64
#define HW    4096
#define NCELL 50
#define EPSV  1e-5f
#define SLOPE 0.01f

// ---------------- device scratch ----------------
__device__ float  g_poolT[N_IMG][NCELL][CIN];
__device__ float  g_prior[4][N_IMG][FOUT][36];
__device__ __half g_inp[(size_t)N_IMG * 66 * 66 * 2048];   // NHWC padded feats (fp16)
__device__ __half g_wt[(size_t)9 * FOUT * 2048];           // feats weights [tap][o][c] (fp16)
__device__ __half g_qa[N_IMG][FOUT][480];                  // prior-collapsed A (fp16)
__device__ __half g_lam[N_IMG][HW][480];                   // geometric weights (fp16)
__device__ float  g_conv[N_IMG][FOUT][HW];

__device__ __forceinline__ uint32_t smem_u32(const void* p) {
    uint32_t a;
    asm("{ .reg .u64 t; cvta.to.shared.u64 t, %1; cvt.u32.u64 %0, t; }" : "=r"(a) : "l"(p));
    return a;
}
__device__ __forceinline__ void cp16(uint32_t saddr, const void* gaddr) {
    asm volatile("cp.async.cg.shared.global [%0], [%1], 16;" :: "r"(saddr), "l"(gaddr));
}
#define CP_COMMIT() asm volatile("cp.async.commit_group;" ::: "memory")
#define CP_WAIT2()  asm volatile("cp.async.wait_group 2;" ::: "memory")

#define LDSM4(r, addr) \
    asm volatile("ldmatrix.sync.aligned.m8n8.x4.shared.b16 {%0,%1,%2,%3}, [%4];" \
        : "=r"((r)[0]), "=r"((r)[1]), "=r"((r)[2]), "=r"((r)[3]) : "r"(addr))

__device__ __forceinline__ void mma_f16(float& c0, float& c1, float& c2, float& c3,
                                        uint32_t a0, uint32_t a1, uint32_t a2, uint32_t a3,
                                        uint32_t b0, uint32_t b1) {
    asm volatile(
        "mma.sync.aligned.m16n8k16.row.col.f32.f16.f16.f32 "
        "{%0,%1,%2,%3}, {%4,%5,%6,%7}, {%8,%9}, {%0,%1,%2,%3};"
        : "+f"(c0), "+f"(c1), "+f"(c2), "+f"(c3)
        : "r"(a0), "r"(a1), "r"(a2), "r"(a3), "r"(b0), "r"(b1));
}

__device__ __forceinline__ void cell_info(int j, int& sz, int& iy, int& ix) {
    if (j == 0)       { sz = 1; iy = 0; ix = 0; }
    else if (j < 5)   { sz = 2; int p = j - 1;  iy = p / 2; ix = p % 2; }
    else if (j < 14)  { sz = 3; int p = j - 5;  iy = p / 3; ix = p % 3; }
    else              { sz = 6; int p = j - 14; iy = p / 6; ix = p % 6; }
}

// ---------------- 1. adaptive pooling ----------------
__global__ void pool_kernel(const float* __restrict__ feats) {
    int nc = blockIdx.x;
    int n = nc / CIN;
    __shared__ float tile[HW];
    const float* src = feats + (size_t)nc * HW;
    for (int i = threadIdx.x; i < HW; i += blockDim.x) tile[i] = src[i];
    __syncthreads();
    int wid = threadIdx.x >> 5, lane = threadIdx.x & 31;
    int c = nc % CIN;
    for (int j = wid; j < NCELL; j += 8) {
        int sz, iy, ix; cell_info(j, sz, iy, ix);
        int hs = iy * H / sz, he = ((iy + 1) * H + sz - 1) / sz;
        int ws_ = ix * W / sz, we = ((ix + 1) * W + sz - 1) / sz;
        int ww = we - ws_;
        int cnt = (he - hs) * ww;
        float sum = 0.f;
        for (int t = lane; t < cnt; t += 32) {
            int r = hs + t / ww, col = ws_ + t % ww;
            sum += tile[r * W + col];
        }
        #pragma unroll
        for (int o = 16; o > 0; o >>= 1) sum += __shfl_xor_sync(0xffffffffu, sum, o);
        if (lane == 0) g_poolT[n][j][c] = sum / (float)cnt;
    }
}

// ---------------- 2. fused 1x1 conv + BN + leaky relu ----------------
__global__ void conv1x1bn_kernel(const float* __restrict__ w0, const float* __restrict__ w1,
                                 const float* __restrict__ w2, const float* __restrict__ w3,
                                 const float* __restrict__ g0, const float* __restrict__ b0,
                                 const float* __restrict__ g1, const float* __restrict__ b1,
                                 const float* __restrict__ g2, const float* __restrict__ b2,
                                 const float* __restrict__ g3, const float* __restrict__ b3) {
    int og = blockIdx.x, br = blockIdx.y;
    const float* wsrc = (br == 0) ? w0 : (br == 1) ? w1 : (br == 2) ? w2 : w3;
    const float* gam  = (br == 0) ? g0 : (br == 1) ? g1 : (br == 2) ? g2 : g3;
    const float* bet  = (br == 0) ? b0 : (br == 1) ? b1 : (br == 2) ? b2 : b3;
    int o0 = og * 4;
    __shared__ float sw[4][CIN];
    for (int i = threadIdx.x; i < 4 * CIN; i += 256)
        sw[i / CIN][i % CIN] = wsrc[(size_t)(o0 + i / CIN) * CIN + (i % CIN)];
    __syncthreads();
    int sz    = (br == 0) ? 1 : (br == 1) ? 2 : (br == 2) ? 3 : 6;
    int cell0 = (br == 0) ? 0 : (br == 1) ? 1 : (br == 2) ? 5 : 14;
    int pp = sz * sz;
    int np = N_IMG * pp;
    int wid = threadIdx.x >> 5, lane = threadIdx.x & 31;
    for (int j = wid; j < np; j += 8) {
        int n = j / pp, p = j % pp;
        const float* prow = &g_poolT[n][cell0 + p][0];
        float a0 = 0, a1 = 0, a2 = 0, a3 = 0;
        for (int k = lane; k < CIN; k += 32) {
            float v = prow[k];
            a0 += sw[0][k] * v; a1 += sw[1][k] * v;
            a2 += sw[2][k] * v; a3 += sw[3][k] * v;
        }
        #pragma unroll
        for (int o = 16; o > 0; o >>= 1) {
            a0 += __shfl_xor_sync(0xffffffffu, a0, o);
            a1 += __shfl_xor_sync(0xffffffffu, a1, o);
            a2 += __shfl_xor_sync(0xffffffffu, a2, o);
            a3 += __shfl_xor_sync(0xffffffffu, a3, o);
        }
        if (lane == 0) {
            g_prior[br][n][o0 + 0][p] = a0;
            g_prior[br][n][o0 + 1][p] = a1;
            g_prior[br][n][o0 + 2][p] = a2;
            g_prior[br][n][o0 + 3][p] = a3;
        }
    }
    __syncthreads();
    if (wid < 4) {
        int o = o0 + wid;
        int cnt = N_IMG * pp;
        float s = 0.f, sq = 0.f;
        for (int e = lane; e < cnt; e += 32) {
            float v = g_prior[br][e / pp][o][e % pp];
            s += v; sq += v * v;
        }
        #pragma unroll
        for (int k = 16; k > 0; k >>= 1) {
            s  += __shfl_xor_sync(0xffffffffu, s, k);
            sq += __shfl_xor_sync(0xffffffffu, sq, k);
        }
        float mean = s / (float)cnt;
        float var  = sq / (float)cnt - mean * mean;
        float sc = rsqrtf(var + EPSV) * gam[o];
        float sh = bet[o] - mean * sc;
        for (int e = lane; e < cnt; e += 32) {
            float v = g_prior[br][e / pp][o][e % pp];
            v = v * sc + sh;
            g_prior[br][e / pp][o][e % pp] = (v >= 0.f) ? v : SLOPE * v;
        }
    }
}

// ---------------- 3. fused prep (fp16 outputs) ----------------
__global__ void __launch_bounds__(256) prep_kernel(const float* __restrict__ feats,
                                                   const float* __restrict__ wb) {
    __shared__ float sm[9472];
    int tid = threadIdx.x;
    int bid = blockIdx.x;

    if (bid < 4096) {
        int cc = bid & 15, xc = (bid >> 4) & 1, y = (bid >> 5) & 63, img = bid >> 11;
        int c0 = cc * 128, x0 = xc * 32;
        float (*t)[33] = (float(*)[33])sm;
        int cr = tid >> 5, xi = tid & 31;
        #pragma unroll
        for (int s = 0; s < 16; s++) {
            int c = cr + s * 8;
            t[c][xi] = feats[((size_t)(img * CIN + c0 + c)) * HW + y * W + x0 + xi];
        }
        __syncthreads();
        int w = tid >> 5, lane = tid & 31;
        #pragma unroll
        for (int s = 0; s < 4; s++) {
            int x = w + s * 8;
            __half* dst = g_inp + ((size_t)(img * 66 + y + 1) * 66 + x0 + x + 1) * 2048 + c0;
            #pragma unroll
            for (int kk = 0; kk < 4; kk++)
                dst[lane + 32 * kk] = __float2half_rn(t[lane + 32 * kk][x]);
        }
    } else if (bid < 4616) {
        int q = bid - 4096;
        int img = q / 260, b = q % 260;
        int y, x;
        if (b < 66)       { y = 0;  x = b; }
        else if (b < 132) { y = 65; x = b - 66; }
        else if (b < 196) { y = b - 132 + 1; x = 0; }
        else              { y = b - 196 + 1; x = 65; }
        uint32_t* dst = (uint32_t*)(g_inp + ((size_t)(img * 66 + y) * 66 + x) * 2048);
        for (int c = tid; c < 1024; c += 256) dst[c] = 0u;
    } else if (bid < 6664) {
        int q = bid - 4616;
        int o = q >> 2, cg = q & 3, c0 = cg * 512;
        const float* src = wb + ((size_t)o * 4096 + 2048 + c0) * 9;
        for (int i = tid; i < 512 * 9; i += 256) sm[i] = src[i];
        __syncthreads();
        for (int tap = 0; tap < 9; tap++) {
            __half* dst = g_wt + ((size_t)(tap * FOUT + o)) * 2048 + c0;
            for (int c = tid; c < 512; c += 256)
                dst[c] = __float2half_rn(sm[c * 9 + tap]);
        }
    } else if (bid < 6720) {
        int q = bid - 6664;
        int o0 = (q & 3) * 128;
        int gi = q >> 2;
        int br, cl0, nc;
        if (gi == 0)      { br = 0; cl0 = 0; nc = 1; }
        else if (gi == 1) { br = 1; cl0 = 0; nc = 4; }
        else if (gi < 5)  { br = 2; cl0 = (gi - 2) * 3; nc = 3; }
        else              { br = 3; cl0 = (gi - 5) * 4; nc = 4; }
        int cellg0 = (br == 0) ? 0 : (br == 1) ? 1 : (br == 2) ? 5 : 14;
        float (*Wsh)[73] = (float(*)[73])sm;
        float* Psh = sm + 128 * 73;
        int o = tid & 127, img = tid >> 7;
        float acc[4][9];
        #pragma unroll
        for (int i = 0; i < 4; i++)
            #pragma unroll
            for (int j = 0; j < 9; j++) acc[i][j] = 0.f;
        for (int c0 = 0; c0 < 512; c0 += 8) {
            for (int i = tid; i < 128 * 72; i += 256) {
                int oi = i / 72, r = i % 72;
                Wsh[oi][r] = wb[((size_t)(o0 + oi) * 4096 + 512 * br + c0) * 9 + r];
            }
            if (tid < 64) {
                int ii = tid >> 5, rem = tid & 31;
                int ci = rem >> 2, cl = rem & 3;
                if (cl < nc)
                    Psh[(ii * 8 + ci) * 4 + cl] = g_prior[br][ii][c0 + ci][cl0 + cl];
            }
            __syncthreads();
            #pragma unroll
            for (int cc = 0; cc < 8; cc++) {
                float pv[4];
                #pragma unroll
                for (int cl = 0; cl < 4; cl++) pv[cl] = Psh[(img * 8 + cc) * 4 + cl];
                #pragma unroll
                for (int tap = 0; tap < 9; tap++) {
                    float wv = Wsh[o][cc * 9 + tap];
                    #pragma unroll
                    for (int cl = 0; cl < 4; cl++) acc[cl][tap] += wv * pv[cl];
                }
            }
            __syncthreads();
        }
        for (int cl = 0; cl < nc; cl++)
            #pragma unroll
            for (int tap = 0; tap < 9; tap++)
                g_qa[img][o0 + o][(cellg0 + cl0 + cl) * 9 + tap] = __float2half_rn(acc[cl][tap]);
        if (gi == 0) {
            for (int kk = 450; kk < 480; kk++) g_qa[img][o0 + o][kk] = __float2half_rn(0.f);
        }
    } else {
        int q = bid - 6720;
        int pix = q & 4095, img = q >> 12;
        int y = pix >> 6, x = pix & 63;
        __half* dst = &g_lam[img][pix][0];
        for (int i = tid; i < 240; i += 256) ((uint32_t*)dst)[i] = 0u;
        __syncthreads();
        if (tid < 36) {
            int br = tid / 9, tap = tid % 9;
            int ky = tap / 3, kx = tap % 3;
            int yp = y + ky - 1, xp = x + kx - 1;
            if (yp >= 0 && yp < 64 && xp >= 0 && xp < 64) {
                int sz = (br == 0) ? 1 : (br == 1) ? 2 : (br == 2) ? 3 : 6;
                int cellg0 = (br == 0) ? 0 : (br == 1) ? 1 : (br == 2) ? 5 : 14;
                float scale = (float)(sz - 1) / 63.f;
                float yc = yp * scale, xc = xp * scale;
                int y0 = (int)floorf(yc), x0 = (int)floorf(xc);
                int y1 = min(y0 + 1, sz - 1), x1 = min(x0 + 1, sz - 1);
                float wy = yc - (float)y0, wx = xc - (float)x0;
                int ys[2] = {y0, y1}; float wys[2] = {1.f - wy, wy};
                int ny = 2;
                if (y1 == y0) { wys[0] += wys[1]; ny = 1; }
                int xs[2] = {x0, x1}; float wxs[2] = {1.f - wx, wx};
                int nx = 2;
                if (x1 == x0) { wxs[0] += wxs[1]; nx = 1; }
                for (int iy = 0; iy < ny; iy++)
                    for (int ix = 0; ix < nx; ix++) {
                        int k = (cellg0 + ys[iy] * sz + xs[ix]) * 9 + tap;
                        dst[k] = __float2half_rn(wys[iy] * wxs[ix]);
                    }
            }
        }
    }
}

// ---------------- 4. mma.sync fp16 GEMM (256x128, ldmatrix, 4-stage) ----------------
#define NKF 576
#define NK  591
#define PITCHB 80
#define A_STG_B (256 * PITCHB)          // 20480 B
#define B_STG_B (128 * PITCHB)          // 10240 B
#define STG_B   (A_STG_B + B_STG_B)     // 30720 B
#define GEMM_SMEM (4 * STG_B)

__global__ void __launch_bounds__(256, 1) gemm_kernel() {
    extern __shared__ __align__(16) char smemc[];
    __half* smem = (__half*)smemc;
    int tid = threadIdx.x;
    int lane = tid & 31, wid = tid >> 5;
    int n_tile = blockIdx.x;            // 0..63
    int m_tile = blockIdx.y;            // 0..1
    int img = n_tile >> 5;
    int rb  = n_tile & 31;
    int y0 = rb * 2, pix0 = rb * 128;
    int oc0 = m_tile * 256;

    int wm = wid & 3, wn = wid >> 2;    // 4(m) x 2(n)
    int m0 = wm * 64, n0 = wn * 64;
    int g = lane >> 2, cq = lane & 3;

    uint32_t sbase = smem_u32(smem);
    int arow = tid >> 2, aseg = tid & 3;

    int pb0, pb1, lb0, lb1;
    {
        int n, rr, x;
        n = tid >> 2;         rr = n >> 6; x = n & 63; pb0 = (rr * 66 + x) * 2048; lb0 = ((y0 + rr) * 64 + x) * 480;
        n = (tid + 256) >> 2; rr = n >> 6; x = n & 63; pb1 = (rr * 66 + x) * 2048; lb1 = ((y0 + rr) * 64 + x) * 480;
    }
    const __half* inp_base = g_inp + (size_t)((img * 66 + y0) * 66) * 2048 + aseg * 8;
    const __half* lam_base = &g_lam[img][0][0] + aseg * 8;

    float acc[4][8][4];
    #pragma unroll
    for (int mt = 0; mt < 4; mt++)
        #pragma unroll
        for (int nt = 0; nt < 8; nt++)
            #pragma unroll
            for (int e = 0; e < 4; e++) acc[mt][nt][e] = 0.f;

    uint32_t sa_a  = sbase + (uint32_t)(arow * PITCHB + aseg * 16);
    uint32_t sa_b0 = sbase + A_STG_B + (uint32_t)((tid >> 2) * PITCHB + aseg * 16);
    uint32_t sa_b1 = sbase + A_STG_B + (uint32_t)(((tid + 256) >> 2) * PITCHB + aseg * 16);

    // ldmatrix per-lane addresses (within stage 0)
    uint32_t lm_a = sbase + (uint32_t)((m0 + (lane & 15)) * PITCHB + ((lane >> 4) << 4));
    uint32_t lm_b = sbase + A_STG_B +
                    (uint32_t)((n0 + (lane & 7) + ((lane >> 4) << 3)) * PITCHB + ((lane & 8) << 1));

    auto load_chunk = [&](int k, int s) {
        uint32_t soff = (uint32_t)s * STG_B;
        if (k < NKF) {
            int tap = k >> 6;
            int c0 = (k & 63) << 5;
            int ky = tap / 3, kx = tap - ky * 3;
            const __half* wsrc = g_wt + (size_t)(tap * 512 + oc0 + arow) * 2048 + c0 + aseg * 8;
            #pragma unroll
            for (int j = 0; j < 4; j++)
                cp16(sa_a + soff + j * (64 * PITCHB), wsrc + j * (size_t)(64 * 2048));
            const __half* bsrc = inp_base + (ky * 66 + kx) * 2048 + c0;
            cp16(sa_b0 + soff, bsrc + pb0);
            cp16(sa_b1 + soff, bsrc + pb1);
        } else {
            int kk = (k - NKF) << 5;
            const __half* qsrc = &g_qa[img][oc0 + arow][kk] + aseg * 8;
            #pragma unroll
            for (int j = 0; j < 4; j++)
                cp16(sa_a + soff + j * (64 * PITCHB), qsrc + j * (size_t)(64 * 480));
            const __half* lsrc = lam_base + kk;
            cp16(sa_b0 + soff, lsrc + lb0);
            cp16(sa_b1 + soff, lsrc + lb1);
        }
        CP_COMMIT();
    };

    load_chunk(0, 0);
    load_chunk(1, 1);
    load_chunk(2, 2);

    int scomp = 0, sload = 3;
    for (int k = 0; k < NK; k++) {
        CP_WAIT2();
        __syncthreads();
        if (k + 3 < NK) load_chunk(k + 3, sload);
        else            CP_COMMIT();

        uint32_t aoff = lm_a + scomp * STG_B;
        uint32_t boff = lm_b + scomp * STG_B;
        #pragma unroll
        for (int k8 = 0; k8 < 2; k8++) {
            uint32_t kb = k8 * 32;
            uint32_t a[4][4], bq[4][4];
            #pragma unroll
            for (int mt = 0; mt < 4; mt++)
                LDSM4(a[mt], aoff + mt * (16 * PITCHB) + kb);
            #pragma unroll
            for (int ntp = 0; ntp < 4; ntp++)
                LDSM4(bq[ntp], boff + ntp * (16 * PITCHB) + kb);
            #pragma unroll
            for (int mt = 0; mt < 4; mt++)
                #pragma unroll
                for (int nt = 0; nt < 8; nt++) {
                    uint32_t b0 = bq[nt >> 1][(nt & 1) * 2];
                    uint32_t b1 = bq[nt >> 1][(nt & 1) * 2 + 1];
                    mma_f16(acc[mt][nt][0], acc[mt][nt][1], acc[mt][nt][2], acc[mt][nt][3],
                            a[mt][0], a[mt][1], a[mt][2], a[mt][3], b0, b1);
                }
        }
        scomp++; if (scomp == 4) scomp = 0;
        sload++; if (sload == 4) sload = 0;
    }

    #pragma unroll
    for (int mt = 0; mt < 4; mt++) {
        int row = m0 + mt * 16 + g;
        #pragma unroll
        for (int nt = 0; nt < 8; nt++) {
            int col = pix0 + n0 + nt * 8 + 2 * cq;
            *(float2*)&g_conv[img][oc0 + row][col]     = make_float2(acc[mt][nt][0], acc[mt][nt][1]);
            *(float2*)&g_conv[img][oc0 + row + 8][col] = make_float2(acc[mt][nt][2], acc[mt][nt][3]);
        }
    }
}

// ---------------- 5. fused BN stats + finalize (one block per channel) ----------------
__global__ void __launch_bounds__(256) finalize_kernel(const float* __restrict__ gb,
                                                       const float* __restrict__ bb,
                                                       float* __restrict__ out) {
    int c = blockIdx.x, tid = threadIdx.x;
    __shared__ float buf[N_IMG * HW];
    float s = 0.f, sq = 0.f;
    #pragma unroll
    for (int j = 0; j < (N_IMG * HW) / 256; j++) {
        int e = tid + j * 256;
        float v = g_conv[e >> 12][c][e & 4095];
        buf[e] = v;
        s += v; sq += v * v;
    }
    __shared__ float shs[8], shq[8];
    #pragma unroll
    for (int k = 16; k > 0; k >>= 1) {
        s  += __shfl_xor_sync(0xffffffffu, s, k);
        sq += __shfl_xor_sync(0xffffffffu, sq, k);
    }
    if ((tid & 31) == 0) { shs[tid >> 5] = s; shq[tid >> 5] = sq; }
    __syncthreads();
    float ts = 0.f, tq = 0.f;
    #pragma unroll
    for (int k = 0; k < 8; k++) { ts += shs[k]; tq += shq[k]; }
    float mean = ts / (float)(N_IMG * HW);
    float var  = tq / (float)(N_IMG * HW) - mean * mean;
    float sc = rsqrtf(var + EPSV) * gb[c];
    float sh = bb[c] - mean * sc;
    #pragma unroll
    for (int j = 0; j < (N_IMG * HW) / 256; j++) {
        int e = tid + j * 256;
        float v = buf[e] * sc + sh;
        out[(size_t)(e >> 12) * FOUT * HW + (size_t)c * HW + (e & 4095)] =
            (v >= 0.f) ? v : SLOPE * v;
    }
}

// ---------------- launch ----------------
extern "C" void kernel_launch(void* const* d_in, const int* in_sizes, int n_in,
                              void* d_out, int out_size) {
    const float* feats = (const float*)d_in[0];
    const float* w0 = (const float*)d_in[1];
    const float* g0 = (const float*)d_in[2];
    const float* b0 = (const float*)d_in[3];
    const float* w1 = (const float*)d_in[4];
    const float* g1 = (const float*)d_in[5];
    const float* b1 = (const float*)d_in[6];
    const float* w2 = (const float*)d_in[7];
    const float* g2 = (const float*)d_in[8];
    const float* b2 = (const float*)d_in[9];
    const float* w3 = (const float*)d_in[10];
    const float* g3 = (const float*)d_in[11];
    const float* b3 = (const float*)d_in[12];
    const float* wb = (const float*)d_in[13];
    const float* gb = (const float*)d_in[14];
    const float* bb = (const float*)d_in[15];

    static int smem_set = 0;
    if (!smem_set) {
        cudaFuncSetAttribute(gemm_kernel, cudaFuncAttributeMaxDynamicSharedMemorySize, GEMM_SMEM);
        smem_set = 1;
    }

    pool_kernel<<<N_IMG * CIN, 256>>>(feats);                                   // 0
    conv1x1bn_kernel<<<dim3(128, 4), 256>>>(w0, w1, w2, w3,
                                            g0, b0, g1, b1, g2, b2, g3, b3);    // 1
    prep_kernel<<<14912, 256>>>(feats, wb);                                     // 2
    gemm_kernel<<<dim3(64, 2), 256, GEMM_SMEM>>>();                             // 3 (ncu target)
    finalize_kernel<<<FOUT, 256>>>(gb, bb, (float*)d_out);                      // 4
}